// round 1
// baseline (speedup 1.0000x reference)
#include <cuda_runtime.h>

#define NN   64
#define CHN  128
#define TTOT 2048
#define SS   9
#define EPS_ 1e-5f

#define CO 64            // output channels per block
#define CI (CO + 8)      // input rows incl. channel halo
#define TT 256           // t-tile
#define NTHREADS 256
#define CG 16            // output channels per thread-group (4 groups of 64 threads)
#define TB 4             // t per thread (float4)
#define CB 8             // register-blocked output channels per chunk
#define NCHUNK (CG / CB)

#define SMEM_FLOATS (CI * TT + CO * SS)

__device__ float g_sum[CHN];
__device__ float g_sq[CHN];
__device__ float g_a[CHN];
__device__ float g_b[CHN];

__global__ void zero_stats_kernel() {
    int i = threadIdx.x;
    if (i < CHN) { g_sum[i] = 0.f; g_sq[i] = 0.f; }
}

__global__ void finalize_stats_kernel(const float* __restrict__ gamma,
                                      const float* __restrict__ beta) {
    int c = threadIdx.x;
    if (c < CHN) {
        const float inv = 1.0f / (float)((long long)NN * TTOT);
        float mean = g_sum[c] * inv;
        float var  = g_sq[c] * inv - mean * mean;
        float a = gamma[c] * rsqrtf(var + EPS_);
        g_a[c] = a;
        g_b[c] = beta[c] - mean * a;
    }
}

template <bool STATS>
__global__ __launch_bounds__(NTHREADS)
void conv_kernel(const float* __restrict__ x,
                 const float* __restrict__ wght,
                 float* __restrict__ out) {
    extern __shared__ float smem[];
    float* xs = smem;               // [CI][TT], shifted + zero-padded input
    float* sw = smem + CI * TT;     // [CO][SS]

    const int t0  = blockIdx.x * TT;
    const int c0  = blockIdx.y * CO;
    const int n   = blockIdx.z;
    const int tid = threadIdx.x;

    // --- load weights for this block's output channels ---
    for (int i = tid; i < CO * SS; i += NTHREADS)
        sw[i] = wght[c0 * SS + i];

    // --- load shifted input tile (shift applied here -> aligned compute) ---
    const float* xn = x + (size_t)n * CHN * TTOT;
    for (int idx = tid; idx < CI * TT; idx += NTHREADS) {
        int r   = idx >> 8;          // TT == 256
        int col = idx & (TT - 1);
        int cc  = c0 - 4 + r;
        float v = 0.f;
        if ((unsigned)cc < CHN) {
            int sh  = cc % SS - 4;   // (c % 9) - 4
            int src = t0 + col - sh;
            if ((unsigned)src < TTOT) v = xn[cc * TTOT + src];
        }
        xs[idx] = v;
    }
    __syncthreads();

    const int tg      = tid >> 6;    // 0..3 channel group
    const int ttl     = tid & 63;    // t-quad index
    const int colbase = ttl * TB;

    #pragma unroll
    for (int chunk = 0; chunk < NCHUNK; ++chunk) {
        const int cb_local = tg * CG + chunk * CB;  // local output chan base

        float acc[CB][TB];
        #pragma unroll
        for (int j = 0; j < CB; ++j)
            #pragma unroll
            for (int k = 0; k < TB; ++k) acc[j][k] = 0.f;

        // input row (local) = cb_local + j + s ; iterate i = j+s in [0, CB+8)
        #pragma unroll
        for (int i = 0; i < CB + SS - 1; ++i) {
            const float4 v = *(const float4*)&xs[(cb_local + i) * TT + colbase];
            #pragma unroll
            for (int j = 0; j < CB; ++j) {
                const int s = i - j;
                if (s >= 0 && s < SS) {
                    const float w = sw[(cb_local + j) * SS + s];
                    acc[j][0] = fmaf(w, v.x, acc[j][0]);
                    acc[j][1] = fmaf(w, v.y, acc[j][1]);
                    acc[j][2] = fmaf(w, v.z, acc[j][2]);
                    acc[j][3] = fmaf(w, v.w, acc[j][3]);
                }
            }
        }

        if (STATS) {
            #pragma unroll
            for (int j = 0; j < CB; ++j) {
                float ps = acc[j][0] + acc[j][1] + acc[j][2] + acc[j][3];
                float pq = acc[j][0] * acc[j][0] + acc[j][1] * acc[j][1]
                         + acc[j][2] * acc[j][2] + acc[j][3] * acc[j][3];
                // warp = 32 lanes with identical channel set, distinct t -> reduce
                #pragma unroll
                for (int o = 16; o > 0; o >>= 1) {
                    ps += __shfl_xor_sync(0xffffffffu, ps, o);
                    pq += __shfl_xor_sync(0xffffffffu, pq, o);
                }
                if ((tid & 31) == 0) {
                    atomicAdd(&g_sum[c0 + cb_local + j], ps);
                    atomicAdd(&g_sq [c0 + cb_local + j], pq);
                }
            }
        } else {
            #pragma unroll
            for (int j = 0; j < CB; ++j) {
                const int cg = c0 + cb_local + j;
                const float a = g_a[cg];
                const float b = g_b[cg];
                float4 o;
                o.x = fmaxf(fmaf(a, acc[j][0], b), 0.f);
                o.y = fmaxf(fmaf(a, acc[j][1], b), 0.f);
                o.z = fmaxf(fmaf(a, acc[j][2], b), 0.f);
                o.w = fmaxf(fmaf(a, acc[j][3], b), 0.f);
                *(float4*)&out[((size_t)n * CHN + cg) * TTOT + t0 + colbase] = o;
            }
        }
    }
}

extern "C" void kernel_launch(void* const* d_in, const int* in_sizes, int n_in,
                              void* d_out, int out_size) {
    const float* x     = (const float*)d_in[0];
    const float* w     = (const float*)d_in[1];
    const float* gamma = (const float*)d_in[2];
    const float* beta  = (const float*)d_in[3];
    float* out = (float*)d_out;

    const int smem_bytes = SMEM_FLOATS * (int)sizeof(float);
    cudaFuncSetAttribute((const void*)conv_kernel<true>,
                         cudaFuncAttributeMaxDynamicSharedMemorySize, smem_bytes);
    cudaFuncSetAttribute((const void*)conv_kernel<false>,
                         cudaFuncAttributeMaxDynamicSharedMemorySize, smem_bytes);

    dim3 grid(TTOT / TT, CHN / CO, NN);

    zero_stats_kernel<<<1, 128>>>();
    conv_kernel<true><<<grid, NTHREADS, smem_bytes>>>(x, w, nullptr);
    finalize_stats_kernel<<<1, 128>>>(gamma, beta);
    conv_kernel<false><<<grid, NTHREADS, smem_bytes>>>(x, w, out);
}

// round 3
// speedup vs baseline: 1.6930x; 1.6930x over previous
#include <cuda_runtime.h>

#define NN   64
#define CHN  128
#define TTOT 2048
#define SS   9
#define EPS_ 1e-5f

#define CO 64            // output channels per block
#define CI (CO + 8)      // input rows incl. channel halo
#define TT 256           // t-tile
#define NTHREADS 256
#define CG 16            // output channels per thread-group (4 groups of 64 threads)
#define TB 4             // t per thread (float4)
#define CB 8             // register-blocked output channels per chunk
#define NCHUNK (CG / CB)

#define SMEM_FLOATS (CI * TT + CO * SS)

__device__ float g_sum[CHN];
__device__ float g_sq[CHN];
__device__ float g_a[CHN];
__device__ float g_b[CHN];

__global__ void zero_stats_kernel() {
    int i = threadIdx.x;
    if (i < CHN) { g_sum[i] = 0.f; g_sq[i] = 0.f; }
}

__global__ void finalize_stats_kernel(const float* __restrict__ gamma,
                                      const float* __restrict__ beta) {
    int c = threadIdx.x;
    if (c < CHN) {
        const float inv = 1.0f / (float)((long long)NN * TTOT);
        float mean = g_sum[c] * inv;
        float var  = g_sq[c] * inv - mean * mean;
        float a = gamma[c] * rsqrtf(var + EPS_);
        g_a[c] = a;
        g_b[c] = beta[c] - mean * a;
    }
}

template <bool STATS>
__global__ __launch_bounds__(NTHREADS, 3)
void conv_kernel(const float* __restrict__ x,
                 const float* __restrict__ wght,
                 float* __restrict__ out) {
    extern __shared__ float smem[];
    float* xs = smem;               // [CI][TT], shifted + zero-padded input
    float* sw = smem + CI * TT;     // [CO][SS]

    const int t0  = blockIdx.x * TT;
    const int c0  = blockIdx.y * CO;
    const int n   = blockIdx.z;
    const int tid = threadIdx.x;
    const int q   = tid & 63;       // quad (float4) index within a row
    const int rg  = tid >> 6;       // row subgroup 0..3

    // --- load weights for this block's output channels ---
    #pragma unroll
    for (int i = tid; i < CO * SS; i += NTHREADS)
        sw[i] = wght[c0 * SS + i];

    // --- fully-unrolled shifted tile load: max MLP, predicated scalar LDG ---
    const float* xn = x + (size_t)n * CHN * TTOT;
    #pragma unroll
    for (int it = 0; it < CI / 4; ++it) {           // 18 iterations, compile-time
        const int r  = it * 4 + rg;                 // smem row
        const int cc = c0 - 4 + r;                  // global channel
        float4 v = make_float4(0.f, 0.f, 0.f, 0.f);
        if ((unsigned)cc < CHN) {
            const int sh = cc % SS - 4;             // (c % 9) - 4
            const int s0 = t0 + q * 4 - sh;         // source t of first elem
            const float* p = xn + (size_t)cc * TTOT + s0;
            // predicated scalar loads (shift breaks 16B alignment)
            if ((unsigned)(s0 + 0) < TTOT) v.x = p[0];
            if ((unsigned)(s0 + 1) < TTOT) v.y = p[1];
            if ((unsigned)(s0 + 2) < TTOT) v.z = p[2];
            if ((unsigned)(s0 + 3) < TTOT) v.w = p[3];
        }
        *(float4*)&xs[r * TT + q * 4] = v;          // aligned STS.128
    }
    __syncthreads();

    const int tg      = tid >> 6;    // 0..3 channel group
    const int ttl     = tid & 63;    // t-quad index
    const int colbase = ttl * TB;

    #pragma unroll
    for (int chunk = 0; chunk < NCHUNK; ++chunk) {
        const int cb_local = tg * CG + chunk * CB;  // local output chan base

        float acc[CB][TB];
        #pragma unroll
        for (int j = 0; j < CB; ++j)
            #pragma unroll
            for (int k = 0; k < TB; ++k) acc[j][k] = 0.f;

        // input row (local) = cb_local + j + s ; iterate i = j+s in [0, CB+8)
        #pragma unroll
        for (int i = 0; i < CB + SS - 1; ++i) {
            const float4 v = *(const float4*)&xs[(cb_local + i) * TT + colbase];
            #pragma unroll
            for (int j = 0; j < CB; ++j) {
                const int s = i - j;
                if (s >= 0 && s < SS) {
                    const float w = sw[(cb_local + j) * SS + s];
                    acc[j][0] = fmaf(w, v.x, acc[j][0]);
                    acc[j][1] = fmaf(w, v.y, acc[j][1]);
                    acc[j][2] = fmaf(w, v.z, acc[j][2]);
                    acc[j][3] = fmaf(w, v.w, acc[j][3]);
                }
            }
        }

        if (STATS) {
            #pragma unroll
            for (int j = 0; j < CB; ++j) {
                float ps = acc[j][0] + acc[j][1] + acc[j][2] + acc[j][3];
                float pq = acc[j][0] * acc[j][0] + acc[j][1] * acc[j][1]
                         + acc[j][2] * acc[j][2] + acc[j][3] * acc[j][3];
                #pragma unroll
                for (int o = 16; o > 0; o >>= 1) {
                    ps += __shfl_xor_sync(0xffffffffu, ps, o);
                    pq += __shfl_xor_sync(0xffffffffu, pq, o);
                }
                if ((tid & 31) == 0) {
                    atomicAdd(&g_sum[c0 + cb_local + j], ps);
                    atomicAdd(&g_sq [c0 + cb_local + j], pq);
                }
            }
        } else {
            #pragma unroll
            for (int j = 0; j < CB; ++j) {
                const int cg = c0 + cb_local + j;
                const float a = g_a[cg];
                const float b = g_b[cg];
                float4 o;
                o.x = fmaxf(fmaf(a, acc[j][0], b), 0.f);
                o.y = fmaxf(fmaf(a, acc[j][1], b), 0.f);
                o.z = fmaxf(fmaf(a, acc[j][2], b), 0.f);
                o.w = fmaxf(fmaf(a, acc[j][3], b), 0.f);
                *(float4*)&out[((size_t)n * CHN + cg) * TTOT + t0 + colbase] = o;
            }
        }
    }
}

extern "C" void kernel_launch(void* const* d_in, const int* in_sizes, int n_in,
                              void* d_out, int out_size) {
    const float* x     = (const float*)d_in[0];
    const float* w     = (const float*)d_in[1];
    const float* gamma = (const float*)d_in[2];
    const float* beta  = (const float*)d_in[3];
    float* out = (float*)d_out;

    const int smem_bytes = SMEM_FLOATS * (int)sizeof(float);
    cudaFuncSetAttribute((const void*)conv_kernel<true>,
                         cudaFuncAttributeMaxDynamicSharedMemorySize, smem_bytes);
    cudaFuncSetAttribute((const void*)conv_kernel<false>,
                         cudaFuncAttributeMaxDynamicSharedMemorySize, smem_bytes);

    dim3 grid(TTOT / TT, CHN / CO, NN);

    zero_stats_kernel<<<1, 128>>>();
    conv_kernel<true><<<grid, NTHREADS, smem_bytes>>>(x, w, nullptr);
    finalize_stats_kernel<<<1, 128>>>(gamma, beta);
    conv_kernel<false><<<grid, NTHREADS, smem_bytes>>>(x, w, out);
}

// round 4
// speedup vs baseline: 2.9771x; 1.7585x over previous
#include <cuda_runtime.h>

#define NN   64
#define CHN  128
#define TTOT 2048
#define SS   9
#define EPS_ 1e-5f

#define CO 64            // output channels per block
#define CI (CO + 8)      // input rows incl. channel halo
#define TT 128           // t-tile
#define NTHREADS 256
#define CB 8             // register-blocked output channels per thread
#define TB 4             // t per thread (float4)

#define SMEM_FLOATS (CI * TT + CO * SS)
#define STAT_STRIDE 33   // padded row stride for conflict-free reduction

__device__ float g_sum[CHN];
__device__ float g_sq[CHN];
__device__ float g_a[CHN];
__device__ float g_b[CHN];

__global__ void zero_stats_kernel() {
    int i = threadIdx.x;
    if (i < CHN) { g_sum[i] = 0.f; g_sq[i] = 0.f; }
}

__global__ void finalize_stats_kernel(const float* __restrict__ gamma,
                                      const float* __restrict__ beta) {
    int c = threadIdx.x;
    if (c < CHN) {
        const float inv = 1.0f / (float)((long long)NN * TTOT);
        float mean = g_sum[c] * inv;
        float var  = g_sq[c] * inv - mean * mean;
        float a = gamma[c] * rsqrtf(var + EPS_);
        g_a[c] = a;
        g_b[c] = beta[c] - mean * a;
    }
}

template <bool STATS>
__global__ __launch_bounds__(NTHREADS, 4)
void conv_kernel(const float* __restrict__ x,
                 const float* __restrict__ wght,
                 float* __restrict__ out) {
    extern __shared__ float smem[];
    float* xs = smem;               // [CI][TT], shifted + zero-padded input
    float* sw = smem + CI * TT;     // [CO][SS]

    const int t0  = blockIdx.x * TT;
    const int c0  = blockIdx.y * CO;
    const int n   = blockIdx.z;
    const int tid = threadIdx.x;

    // --- weights for this block's output channels ---
    #pragma unroll
    for (int i = tid; i < CO * SS; i += NTHREADS)
        sw[i] = wght[c0 * SS + i];

    // --- shifted tile load: coalesced scalar LDG (1 wavefront each), scalar STS ---
    const float* xn  = x + (size_t)n * CHN * TTOT;
    const int    col = tid & (TT - 1);     // 0..127, unit stride per warp
    const int    rh  = tid >> 7;           // 0/1 : two rows per iteration

    const bool interior = (t0 >= 4) && (t0 + TT + 4 <= TTOT);
    if (interior) {
        #pragma unroll
        for (int it = 0; it < CI / 2; ++it) {
            const int r  = it * 2 + rh;
            const int cc = c0 - 4 + r;               // uniform per (it,rh)
            float v = 0.f;
            if ((unsigned)cc < CHN) {                // uniform predicate
                const int sh = ((cc + 18) % SS) - 4;
                v = xn[(size_t)cc * TTOT + (t0 + col - sh)];
            }
            xs[r * TT + col] = v;
        }
    } else {
        #pragma unroll
        for (int it = 0; it < CI / 2; ++it) {
            const int r  = it * 2 + rh;
            const int cc = c0 - 4 + r;
            float v = 0.f;
            if ((unsigned)cc < CHN) {
                const int sh  = ((cc + 18) % SS) - 4;
                const int src = t0 + col - sh;
                if ((unsigned)src < TTOT) v = xn[(size_t)cc * TTOT + src];
            }
            xs[r * TT + col] = v;
        }
    }
    __syncthreads();

    // --- register-blocked conv: 8 channels x 4 t per thread ---
    const int tg      = tid >> 5;          // 0..7 channel group (one warp)
    const int lane    = tid & 31;
    const int colbase = lane * TB;         // 0..124
    const int cb      = tg * CB;           // local output chan base

    float acc[CB][TB];
    #pragma unroll
    for (int j = 0; j < CB; ++j)
        #pragma unroll
        for (int k = 0; k < TB; ++k) acc[j][k] = 0.f;

    #pragma unroll
    for (int i = 0; i < CB + SS - 1; ++i) {
        const float4 v = *(const float4*)&xs[(cb + i) * TT + colbase];
        #pragma unroll
        for (int j = 0; j < CB; ++j) {
            const int s = i - j;
            if (s >= 0 && s < SS) {
                const float w = sw[(cb + j) * SS + s];
                acc[j][0] = fmaf(w, v.x, acc[j][0]);
                acc[j][1] = fmaf(w, v.y, acc[j][1]);
                acc[j][2] = fmaf(w, v.z, acc[j][2]);
                acc[j][3] = fmaf(w, v.w, acc[j][3]);
            }
        }
    }

    if (STATS) {
        __syncthreads();                    // xs reads done -> reuse as stats area
        float* sums = smem;                 // [CO][STAT_STRIDE]
        float* sqs  = smem + CO * STAT_STRIDE;

        #pragma unroll
        for (int j = 0; j < CB; ++j) {
            float ps = (acc[j][0] + acc[j][1]) + (acc[j][2] + acc[j][3]);
            float pq = fmaf(acc[j][0], acc[j][0],
                       fmaf(acc[j][1], acc[j][1],
                       fmaf(acc[j][2], acc[j][2], acc[j][3] * acc[j][3])));
            sums[(cb + j) * STAT_STRIDE + lane] = ps;
            sqs [(cb + j) * STAT_STRIDE + lane] = pq;
        }
        __syncthreads();

        if (tid < 2 * CO) {                 // 128 threads: one row each
            const int   c    = tid & (CO - 1);
            const bool  isSq = tid >= CO;
            const float* base = (isSq ? sqs : sums) + c * STAT_STRIDE;
            float s = 0.f;
            #pragma unroll
            for (int k = 0; k < 32; ++k) s += base[k];   // stride-33 rows: conflict-free
            atomicAdd(isSq ? &g_sq[c0 + c] : &g_sum[c0 + c], s);
        }
    } else {
        #pragma unroll
        for (int j = 0; j < CB; ++j) {
            const int   cg = c0 + cb + j;
            const float a  = g_a[cg];
            const float b  = g_b[cg];
            float4 o;
            o.x = fmaxf(fmaf(a, acc[j][0], b), 0.f);
            o.y = fmaxf(fmaf(a, acc[j][1], b), 0.f);
            o.z = fmaxf(fmaf(a, acc[j][2], b), 0.f);
            o.w = fmaxf(fmaf(a, acc[j][3], b), 0.f);
            *(float4*)&out[((size_t)n * CHN + cg) * TTOT + t0 + colbase] = o;
        }
    }
}

extern "C" void kernel_launch(void* const* d_in, const int* in_sizes, int n_in,
                              void* d_out, int out_size) {
    const float* x     = (const float*)d_in[0];
    const float* w     = (const float*)d_in[1];
    const float* gamma = (const float*)d_in[2];
    const float* beta  = (const float*)d_in[3];
    float* out = (float*)d_out;

    const int smem_bytes = SMEM_FLOATS * (int)sizeof(float);
    cudaFuncSetAttribute((const void*)conv_kernel<true>,
                         cudaFuncAttributeMaxDynamicSharedMemorySize, smem_bytes);
    cudaFuncSetAttribute((const void*)conv_kernel<false>,
                         cudaFuncAttributeMaxDynamicSharedMemorySize, smem_bytes);

    dim3 grid(TTOT / TT, CHN / CO, NN);

    zero_stats_kernel<<<1, 128>>>();
    conv_kernel<true><<<grid, NTHREADS, smem_bytes>>>(x, w, nullptr);
    finalize_stats_kernel<<<1, 128>>>(gamma, beta);
    conv_kernel<false><<<grid, NTHREADS, smem_bytes>>>(x, w, out);
}